// round 12
// baseline (speedup 1.0000x reference)
#include <cuda_runtime.h>
#include <math.h>

// Problem dims
#define BB 2
#define SS 2048
#define DD 1024
#define HH 16
#define HD 64
#define ROWS (BB*SS)          // 4096
#define EPS 1e-6f

typedef unsigned long long u64;

// ---------------- packed f32x2 helpers (sm_103a FFMA2 pipe) ----------------
__device__ __forceinline__ u64 fma2(u64 a, u64 b, u64 c) {
    u64 d;
    asm("fma.rn.f32x2 %0, %1, %2, %3;" : "=l"(d) : "l"(a), "l"(b), "l"(c));
    return d;
}
__device__ __forceinline__ u64 mul2(u64 a, u64 b) {
    u64 d;
    asm("mul.rn.f32x2 %0, %1, %2;" : "=l"(d) : "l"(a), "l"(b));
    return d;
}
__device__ __forceinline__ u64 pack2(float lo, float hi) {
    u64 d;
    asm("mov.b64 %0, {%1, %2};" : "=l"(d) : "f"(lo), "f"(hi));
    return d;
}
__device__ __forceinline__ float lo2(u64 a) { return __uint_as_float((unsigned)a); }
__device__ __forceinline__ float hi2(u64 a) { return __uint_as_float((unsigned)(a >> 32)); }
__device__ __forceinline__ float ex2(float x) {
    float r;
    asm("ex2.approx.f32 %0, %1;" : "=f"(r) : "f"(x));
    return r;
}

// ---------------- tf32 mma helpers -----------------------------------------
__device__ __forceinline__ float cvt_tf32(float x) {
    float r;
    asm("cvt.rna.tf32.f32 %0, %1;" : "=f"(r) : "f"(x));
    return r;
}
__device__ __forceinline__ void mma_tf32(
    float& c0, float& c1, float& c2, float& c3,
    unsigned a0, unsigned a1, unsigned a2, unsigned a3,
    unsigned b0, unsigned b1)
{
    asm volatile(
        "mma.sync.aligned.m16n8k8.row.col.f32.tf32.tf32.f32 "
        "{%0,%1,%2,%3}, {%4,%5,%6,%7}, {%8,%9}, {%0,%1,%2,%3};"
        : "+f"(c0), "+f"(c1), "+f"(c2), "+f"(c3)
        : "r"(a0), "r"(a1), "r"(a2), "r"(a3), "r"(b0), "r"(b1));
}

// ---------------- cp.async helpers ------------------------------------------
__device__ __forceinline__ void cpa16(void* dst, const void* src) {
    unsigned d = (unsigned)__cvta_generic_to_shared(dst);
    asm volatile("cp.async.cg.shared.global [%0], [%1], 16;" :: "r"(d), "l"(src));
}
#define CP_COMMIT()  asm volatile("cp.async.commit_group;")
#define CP_WAIT(N)   asm volatile("cp.async.wait_group %0;" :: "n"(N))

// ---------------- scratch (device globals; no allocation allowed) ----------
__device__ float g_xn  [ROWS * DD];
__device__ float g_qkv [ROWS * 3 * DD];
__device__ float g_q   [BB * HH * SS * HD];  // [b,h,s,d]
__device__ float g_k   [BB * HH * SS * HD];
__device__ float g_v   [BB * HH * SS * HD];
__device__ float g_attn[ROWS * DD];          // [b,s,h*64+d]
__device__ int   g_ticket;

// ---------------- kernel 1: row LayerNorm over D=1024 ---------------------
__global__ __launch_bounds__(256) void ln_kernel(
    const float* __restrict__ x, const float* __restrict__ scale,
    const float* __restrict__ bias, float* __restrict__ y)
{
    __shared__ float sh[8];
    const int t = threadIdx.x;
    const size_t row = blockIdx.x;
    const float* xr = x + row * DD;

    float v0 = xr[t], v1 = xr[t + 256], v2 = xr[t + 512], v3 = xr[t + 768];

    float s = v0 + v1 + v2 + v3;
    #pragma unroll
    for (int o = 16; o; o >>= 1) s += __shfl_xor_sync(0xffffffffu, s, o);
    if ((t & 31) == 0) sh[t >> 5] = s;
    __syncthreads();
    float tot = 0.f;
    #pragma unroll
    for (int i = 0; i < 8; i++) tot += sh[i];
    const float mean = tot * (1.f / 1024.f);

    float a0 = v0 - mean, a1 = v1 - mean, a2 = v2 - mean, a3 = v3 - mean;
    float sq = a0*a0 + a1*a1 + a2*a2 + a3*a3;
    #pragma unroll
    for (int o = 16; o; o >>= 1) sq += __shfl_xor_sync(0xffffffffu, sq, o);
    __syncthreads();
    if ((t & 31) == 0) sh[t >> 5] = sq;
    __syncthreads();
    float tsq = 0.f;
    #pragma unroll
    for (int i = 0; i < 8; i++) tsq += sh[i];
    const float rstd = rsqrtf(tsq * (1.f / 1024.f) + EPS);

    float* yr = y + row * DD;
    yr[t      ] = a0 * rstd * scale[t      ] + bias[t      ];
    yr[t + 256] = a1 * rstd * scale[t + 256] + bias[t + 256];
    yr[t + 512] = a2 * rstd * scale[t + 512] + bias[t + 512];
    yr[t + 768] = a3 * rstd * scale[t + 768] + bias[t + 768];
}

// ---------------- kernel 2: 3xTF32 GEMM v2 ---------------------------------
// 128x128 tile, KT=16, 256 thr = 8 warps (2m x 4n), warp tile 64x32.
// Smem per stage: A[128 rows][36 floats] + B[128 cols][36 floats] where each
// (row, hs, t) float4 = (hi_k, lo_k, hi_{k+4}, lo_{k+4}).  Row stride 36
// floats = 9 x 16B units -> fragment LDS.128 verified bank-conflict-free.
// Register-staged double buffering: LDG next k-tile at iter start, cvt+STS
// at iter end, ONE __syncthreads per iter. 12 LDS.128 + 48 mma per k8.
#define GBOFF  4608          // floats: A region size (128*36)
#define GSTAGE 9216          // floats per stage (A + B)

__device__ __forceinline__ void g_store(float* sb, int tid,
    float4 ra0, float4 ra1, float4 rb0, float4 rb1)
{
    const int am = tid >> 1, ahs = tid & 1;
    float* Ab = sb + am * 36 + ahs * 16;
    float va[8] = {ra0.x, ra0.y, ra0.z, ra0.w, ra1.x, ra1.y, ra1.z, ra1.w};
    #pragma unroll
    for (int tt = 0; tt < 4; tt++) {
        float h0 = cvt_tf32(va[tt]);
        float h1 = cvt_tf32(va[tt + 4]);
        float4 o; o.x = h0; o.y = va[tt] - h0; o.z = h1; o.w = va[tt + 4] - h1;
        *(float4*)(Ab + tt * 4) = o;
    }
    const int bk = tid >> 4, bn = (tid & 15) * 8;
    const int bhs = bk >> 3, kk = bk & 7, bt = kk & 3, bu = kk >> 2;
    float* Bb = sb + GBOFF + bhs * 16 + bt * 4 + bu * 2;
    float vb[8] = {rb0.x, rb0.y, rb0.z, rb0.w, rb1.x, rb1.y, rb1.z, rb1.w};
    #pragma unroll
    for (int j = 0; j < 8; j++) {
        float h = cvt_tf32(vb[j]);
        float2 o; o.x = h; o.y = vb[j] - h;
        *(float2*)(Bb + (bn + j) * 36) = o;
    }
}

__device__ __forceinline__ void g_compute(const float* Sa,
    int warp_m, int warp_n, int g, int t, float (&c)[4][4][4])
{
    const float* Sb = Sa + GBOFF;
    #pragma unroll
    for (int hs = 0; hs < 2; hs++) {
        float4 fa0[4], fa1[4], fb[4];
        #pragma unroll
        for (int mi = 0; mi < 4; mi++) {
            const int r = warp_m * 64 + mi * 16 + g;
            fa0[mi] = *(const float4*)(Sa + r * 36 + hs * 16 + t * 4);
            fa1[mi] = *(const float4*)(Sa + (r + 8) * 36 + hs * 16 + t * 4);
        }
        #pragma unroll
        for (int ni = 0; ni < 4; ni++) {
            const int n = warp_n * 32 + ni * 8 + g;
            fb[ni] = *(const float4*)(Sb + n * 36 + hs * 16 + t * 4);
        }
        // hi*hi
        #pragma unroll
        for (int mi = 0; mi < 4; mi++)
            #pragma unroll
            for (int ni = 0; ni < 4; ni++)
                mma_tf32(c[mi][ni][0], c[mi][ni][1], c[mi][ni][2], c[mi][ni][3],
                    __float_as_uint(fa0[mi].x), __float_as_uint(fa1[mi].x),
                    __float_as_uint(fa0[mi].z), __float_as_uint(fa1[mi].z),
                    __float_as_uint(fb[ni].x),  __float_as_uint(fb[ni].z));
        // hi*lo
        #pragma unroll
        for (int mi = 0; mi < 4; mi++)
            #pragma unroll
            for (int ni = 0; ni < 4; ni++)
                mma_tf32(c[mi][ni][0], c[mi][ni][1], c[mi][ni][2], c[mi][ni][3],
                    __float_as_uint(fa0[mi].x), __float_as_uint(fa1[mi].x),
                    __float_as_uint(fa0[mi].z), __float_as_uint(fa1[mi].z),
                    __float_as_uint(fb[ni].y),  __float_as_uint(fb[ni].w));
        // lo*hi
        #pragma unroll
        for (int mi = 0; mi < 4; mi++)
            #pragma unroll
            for (int ni = 0; ni < 4; ni++)
                mma_tf32(c[mi][ni][0], c[mi][ni][1], c[mi][ni][2], c[mi][ni][3],
                    __float_as_uint(fa0[mi].y), __float_as_uint(fa1[mi].y),
                    __float_as_uint(fa0[mi].w), __float_as_uint(fa1[mi].w),
                    __float_as_uint(fb[ni].x),  __float_as_uint(fb[ni].z));
    }
}

__global__ __launch_bounds__(256, 1) void sgemm_tf32(
    const float* __restrict__ A, const float* __restrict__ B,
    const float* __restrict__ bias, float* __restrict__ C,
    int M, int N, int K)
{
    extern __shared__ float gsm[];

    const int tid = threadIdx.x;
    const int wid = tid >> 5;
    const int lane = tid & 31;
    const int g = lane >> 2;
    const int t = lane & 3;
    const int warp_m = wid >> 2;
    const int warp_n = wid & 3;
    const int rowBase = blockIdx.y * 128;
    const int colBase = blockIdx.x * 128;

    const float* Ag = A + (size_t)(rowBase + (tid >> 1)) * K + (tid & 1) * 8;
    const float* Bg = B + (size_t)(tid >> 4) * N + colBase + (tid & 15) * 8;

    float c[4][4][4];
    #pragma unroll
    for (int mi = 0; mi < 4; mi++)
        #pragma unroll
        for (int ni = 0; ni < 4; ni++)
            #pragma unroll
            for (int e = 0; e < 4; e++) c[mi][ni][e] = 0.f;

    const int NIT = K >> 4;

    // prologue: tile0 -> stage0; prefetch tile1
    float4 ra0 = *(const float4*)(Ag);
    float4 ra1 = *(const float4*)(Ag + 4);
    float4 rb0 = *(const float4*)(Bg);
    float4 rb1 = *(const float4*)(Bg + 4);
    g_store(gsm, tid, ra0, ra1, rb0, rb1);
    if (NIT > 1) {
        ra0 = *(const float4*)(Ag + 16);
        ra1 = *(const float4*)(Ag + 20);
        rb0 = *(const float4*)(Bg + (size_t)16 * N);
        rb1 = *(const float4*)(Bg + (size_t)16 * N + 4);
    }
    __syncthreads();

    int i = 0;
    for (;;) {
        g_compute(gsm + (i & 1) * GSTAGE, warp_m, warp_n, g, t, c);
        if (++i == NIT) break;
        g_store(gsm + (i & 1) * GSTAGE, tid, ra0, ra1, rb0, rb1);
        if (i + 1 < NIT) {
            const int k0 = (i + 1) * 16;
            ra0 = *(const float4*)(Ag + k0);
            ra1 = *(const float4*)(Ag + k0 + 4);
            rb0 = *(const float4*)(Bg + (size_t)k0 * N);
            rb1 = *(const float4*)(Bg + (size_t)k0 * N + 4);
        }
        __syncthreads();
    }

    // epilogue: bias + store
    #pragma unroll
    for (int ni = 0; ni < 4; ni++) {
        const int col = colBase + warp_n * 32 + ni * 8 + 2 * t;
        const float2 bb = *(const float2*)(bias + col);
        #pragma unroll
        for (int mi = 0; mi < 4; mi++) {
            const int row = rowBase + warp_m * 64 + mi * 16 + g;
            float2 o0, o1;
            o0.x = c[mi][ni][0] + bb.x;  o0.y = c[mi][ni][1] + bb.y;
            o1.x = c[mi][ni][2] + bb.x;  o1.y = c[mi][ni][3] + bb.y;
            *(float2*)(C + (size_t)row * N + col)       = o0;
            *(float2*)(C + (size_t)(row + 8) * N + col) = o1;
        }
    }
}

// ---------------- kernel 3: per-head LN (q,k) + RoPE + transpose ----------
__global__ __launch_bounds__(128) void qk_rope_kernel(
    const float* __restrict__ qkv,
    const float* __restrict__ q_scale, const float* __restrict__ k_scale,
    float* __restrict__ Q, float* __restrict__ K, float* __restrict__ V)
{
    const int w = blockIdx.x * 4 + (threadIdx.x >> 5);
    const int lane = threadIdx.x & 31;
    const int h = w % HH;
    const int s = (w / HH) % SS;
    const int b = w / (HH * SS);

    const float* row = qkv + (size_t)(b * SS + s) * (3 * DD) + h * HD;
    float q0 = row[lane],        q1 = row[lane + 32];
    float k0 = row[DD + lane],   k1 = row[DD + lane + 32];
    float v0 = row[2*DD + lane], v1 = row[2*DD + lane + 32];

    float mu = q0 + q1;
    #pragma unroll
    for (int o = 16; o; o >>= 1) mu += __shfl_xor_sync(0xffffffffu, mu, o);
    mu *= (1.f / 64.f);
    float a0 = q0 - mu, a1 = q1 - mu;
    float var = a0 * a0 + a1 * a1;
    #pragma unroll
    for (int o = 16; o; o >>= 1) var += __shfl_xor_sync(0xffffffffu, var, o);
    float r = rsqrtf(var * (1.f / 64.f) + EPS);
    float yq0 = a0 * r * q_scale[lane], yq1 = a1 * r * q_scale[lane + 32];

    mu = k0 + k1;
    #pragma unroll
    for (int o = 16; o; o >>= 1) mu += __shfl_xor_sync(0xffffffffu, mu, o);
    mu *= (1.f / 64.f);
    a0 = k0 - mu; a1 = k1 - mu;
    var = a0 * a0 + a1 * a1;
    #pragma unroll
    for (int o = 16; o; o >>= 1) var += __shfl_xor_sync(0xffffffffu, var, o);
    r = rsqrtf(var * (1.f / 64.f) + EPS);
    float yk0 = a0 * r * k_scale[lane], yk1 = a1 * r * k_scale[lane + 32];

    const float invf = (float)exp(-(double)(2 * lane) / 64.0 * log(10000.0));
    const float ang = (float)s * invf;
    const float c = cosf(ang), sn = sinf(ang);

    float oq0 = yq0 * c - yq1 * sn;
    float oq1 = yq1 * c + yq0 * sn;
    float ok0 = yk0 * c - yk1 * sn;
    float ok1 = yk1 * c + yk0 * sn;

    const size_t base = ((size_t)(b * HH + h) * SS + s) * HD;
    Q[base + lane] = oq0; Q[base + lane + 32] = oq1;
    K[base + lane] = ok0; K[base + lane + 32] = ok1;
    V[base + lane] = v0;  V[base + lane + 32] = v1;
}

// ---------------- kernel 4: flash attention v5 ------------------------------
// Persistent blocks (atomic ticket over 512 tiles, kills wave tail) +
// cp.async double-buffered K/V (hides global latency). Compute identical
// to v4: tid=2m+h, 2 queries/thread, packed f32x2, 8-key batched softmax.
// Dynamic smem: 2 stages x (K 18432 B + V 18432 B) = 73728 B.
#define FL_STAGE 2304        // ull2 per stage (K 1152 + V 1152)
#define FL_VOFF  1152

__device__ __forceinline__ void fl_copy(ulonglong2* dst,
    const ulonglong2* Kg, const ulonglong2* Vg, int tid)
{
    #pragma unroll
    for (int i = 0; i < 8; i++) {
        const int e  = tid + i * 128;
        const int j  = e >> 4;
        const int qq = e & 15;
        const int di = j * 18 + (qq >> 3) * 9 + (qq & 7);
        cpa16(dst + di, Kg + e);
        cpa16(dst + FL_VOFF + di, Vg + e);
    }
    CP_COMMIT();
}

__global__ __launch_bounds__(128, 2) void flash_kernel(
    const float* __restrict__ Q, const float* __restrict__ K,
    const float* __restrict__ V, float* __restrict__ O)
{
    extern __shared__ ulonglong2 dsm[];
    __shared__ int s_tile;

    const int tid = threadIdx.x;
    const int m = tid >> 1;
    const int h = tid & 1;
    const float QSCALE = 0.125f * 1.44269504088896340736f;
    const u64 qsc = pack2(QSCALE, QSCALE);

    for (;;) {
        if (tid == 0) s_tile = atomicAdd(&g_ticket, 1);
        __syncthreads();
        const int tile = s_tile;
        if (tile >= 512) break;

        const int bh = tile >> 4;
        const int q0 = (tile & 15) * 128;
        const int rA = q0 + m;
        const int rB = q0 + 64 + m;

        const ulonglong2* Kg0 = (const ulonglong2*)(K + (size_t)bh * SS * HD);
        const ulonglong2* Vg0 = (const ulonglong2*)(V + (size_t)bh * SS * HD);

        // prologue: chunk 0 -> stage 0
        fl_copy(dsm, Kg0, Vg0, tid);

        // load both query rows' halves, pre-scaled
        u64 qA[16], qB[16];
        {
            const ulonglong2* Qa = (const ulonglong2*)(Q + ((size_t)bh * SS + rA) * HD + h * 32);
            const ulonglong2* Qb = (const ulonglong2*)(Q + ((size_t)bh * SS + rB) * HD + h * 32);
            #pragma unroll
            for (int i = 0; i < 8; i++) {
                ulonglong2 ta = Qa[i];
                qA[2*i] = mul2(ta.x, qsc); qA[2*i+1] = mul2(ta.y, qsc);
                ulonglong2 tb = Qb[i];
                qB[2*i] = mul2(tb.x, qsc); qB[2*i+1] = mul2(tb.y, qsc);
            }
        }

        u64 accA[16], accB[16];
        #pragma unroll
        for (int i = 0; i < 16; i++) { accA[i] = 0ull; accB[i] = 0ull; }
        float la = 0.f, lb = 0.f;

        for (int kt = 0; kt < SS / 64; kt++) {
            if (kt + 1 < SS / 64) {
                fl_copy(dsm + ((kt + 1) & 1) * FL_STAGE,
                        Kg0 + (kt + 1) * 1024, Vg0 + (kt + 1) * 1024, tid);
                CP_WAIT(1);
            } else {
                CP_WAIT(0);
            }
            __syncthreads();

            const ulonglong2* buf = dsm + (kt & 1) * FL_STAGE;
            const ulonglong2* Ksh = buf + h * 9;
            const ulonglong2* Vsh = buf + FL_VOFF + h * 9;

            #pragma unroll 1
            for (int jt = 0; jt < 64; jt += 8) {
                u64 cA[8], cB[8];
                #pragma unroll
                for (int j = 0; j < 8; j++) {
                    const ulonglong2* kr = Ksh + (jt + j) * 18;
                    u64 a = 0ull, b = 0ull;
                    #pragma unroll
                    for (int k4 = 0; k4 < 8; k4++) {
                        ulonglong2 kk = kr[k4];
                        a = fma2(qA[2*k4  ], kk.x, a);
                        a = fma2(qA[2*k4+1], kk.y, a);
                        b = fma2(qB[2*k4  ], kk.x, b);
                        b = fma2(qB[2*k4+1], kk.y, b);
                    }
                    cA[j] = a; cB[j] = b;
                }

                float pA[8], pB[8];
                #pragma unroll
                for (int j = 0; j < 8; j++) {
                    float sa = lo2(cA[j]) + hi2(cA[j]);
                    float sb = lo2(cB[j]) + hi2(cB[j]);
                    sa += __shfl_xor_sync(0xffffffffu, sa, 1);
                    sb += __shfl_xor_sync(0xffffffffu, sb, 1);
                    pA[j] = ex2(sa);
                    pB[j] = ex2(sb);
                }
                #pragma unroll
                for (int j = 0; j < 8; j++) { la += pA[j]; lb += pB[j]; }

                #pragma unroll
                for (int j = 0; j < 8; j++) {
                    const ulonglong2* vr = Vsh + (jt + j) * 18;
                    const u64 ppa = pack2(pA[j], pA[j]);
                    const u64 ppb = pack2(pB[j], pB[j]);
                    #pragma unroll
                    for (int d4 = 0; d4 < 8; d4++) {
                        ulonglong2 vv = vr[d4];
                        accA[2*d4  ] = fma2(ppa, vv.x, accA[2*d4  ]);
                        accA[2*d4+1] = fma2(ppa, vv.y, accA[2*d4+1]);
                        accB[2*d4  ] = fma2(ppb, vv.x, accB[2*d4  ]);
                        accB[2*d4+1] = fma2(ppb, vv.y, accB[2*d4+1]);
                    }
                }
            }
            __syncthreads();
        }

        const int b = bh >> 4, hh = bh & 15;
        const u64 pia = pack2(1.f / la, 1.f / la);
        const u64 pib = pack2(1.f / lb, 1.f / lb);
        ulonglong2* Oa = (ulonglong2*)(O + ((size_t)(b * SS + rA)) * DD + hh * HD + h * 32);
        ulonglong2* Ob = (ulonglong2*)(O + ((size_t)(b * SS + rB)) * DD + hh * HD + h * 32);
        #pragma unroll
        for (int i = 0; i < 8; i++) {
            ulonglong2 ta, tb;
            ta.x = mul2(accA[2*i], pia); ta.y = mul2(accA[2*i+1], pia);
            tb.x = mul2(accB[2*i], pib); tb.y = mul2(accB[2*i+1], pib);
            Oa[i] = ta;
            Ob[i] = tb;
        }
    }
}

// ---------------- launcher -------------------------------------------------
extern "C" void kernel_launch(void* const* d_in, const int* in_sizes, int n_in,
                              void* d_out, int out_size)
{
    const float* x        = (const float*)d_in[0];
    const float* w_qkv    = (const float*)d_in[1];
    const float* b_qkv    = (const float*)d_in[2];
    const float* w_out    = (const float*)d_in[3];
    const float* b_out    = (const float*)d_in[4];
    const float* ln_scale = (const float*)d_in[5];
    const float* ln_bias  = (const float*)d_in[6];
    const float* q_scale  = (const float*)d_in[7];
    const float* k_scale  = (const float*)d_in[8];
    float* out = (float*)d_out;

    float *xn, *qkv, *q, *k, *v, *attn;
    int* ticket;
    cudaGetSymbolAddress((void**)&xn,     g_xn);
    cudaGetSymbolAddress((void**)&qkv,    g_qkv);
    cudaGetSymbolAddress((void**)&q,      g_q);
    cudaGetSymbolAddress((void**)&k,      g_k);
    cudaGetSymbolAddress((void**)&v,      g_v);
    cudaGetSymbolAddress((void**)&attn,   g_attn);
    cudaGetSymbolAddress((void**)&ticket, g_ticket);

    cudaFuncSetAttribute(sgemm_tf32,
        cudaFuncAttributeMaxDynamicSharedMemorySize, 2 * GSTAGE * 4);
    cudaFuncSetAttribute(flash_kernel,
        cudaFuncAttributeMaxDynamicSharedMemorySize, 2 * FL_STAGE * 16);

    // 1) input layernorm
    ln_kernel<<<ROWS, 256>>>(x, ln_scale, ln_bias, xn);

    // 2) QKV projection: [4096,1024] @ [1024,3072]  (3xTF32, double-buffered)
    sgemm_tf32<<<dim3(3 * DD / 128, ROWS / 128), 256, 2 * GSTAGE * 4>>>(
        xn, w_qkv, b_qkv, qkv, ROWS, 3 * DD, DD);

    // 3) head LN + RoPE + layout change
    qk_rope_kernel<<<(BB * SS * HH) / 4, 128>>>(qkv, q_scale, k_scale, q, k, v);

    // 4) attention: persistent grid + atomic tile scheduler
    cudaMemsetAsync(ticket, 0, sizeof(int));
    flash_kernel<<<304, 128, 2 * FL_STAGE * 16>>>(q, k, v, attn);

    // 5) output projection: [4096,1024] @ [1024,1024]  (3xTF32)
    sgemm_tf32<<<dim3(DD / 128, ROWS / 128), 256, 2 * GSTAGE * 4>>>(
        attn, w_out, b_out, out, ROWS, DD, DD);
}

// round 13
// speedup vs baseline: 1.3205x; 1.3205x over previous
#include <cuda_runtime.h>
#include <math.h>

// Problem dims
#define BB 2
#define SS 2048
#define DD 1024
#define HH 16
#define HD 64
#define ROWS (BB*SS)          // 4096
#define EPS 1e-6f

typedef unsigned long long u64;

// ---------------- packed f32x2 helpers (sm_103a FFMA2 pipe) ----------------
__device__ __forceinline__ u64 fma2(u64 a, u64 b, u64 c) {
    u64 d;
    asm("fma.rn.f32x2 %0, %1, %2, %3;" : "=l"(d) : "l"(a), "l"(b), "l"(c));
    return d;
}
__device__ __forceinline__ u64 mul2(u64 a, u64 b) {
    u64 d;
    asm("mul.rn.f32x2 %0, %1, %2;" : "=l"(d) : "l"(a), "l"(b));
    return d;
}
__device__ __forceinline__ u64 pack2(float lo, float hi) {
    u64 d;
    asm("mov.b64 %0, {%1, %2};" : "=l"(d) : "f"(lo), "f"(hi));
    return d;
}
__device__ __forceinline__ float lo2(u64 a) { return __uint_as_float((unsigned)a); }
__device__ __forceinline__ float hi2(u64 a) { return __uint_as_float((unsigned)(a >> 32)); }
__device__ __forceinline__ float ex2(float x) {
    float r;
    asm("ex2.approx.f32 %0, %1;" : "=f"(r) : "f"(x));
    return r;
}

// ---------------- tf32 mma helpers -----------------------------------------
__device__ __forceinline__ float cvt_tf32(float x) {
    float r;
    asm("cvt.rna.tf32.f32 %0, %1;" : "=f"(r) : "f"(x));
    return r;
}
__device__ __forceinline__ void mma_tf32(
    float& c0, float& c1, float& c2, float& c3,
    unsigned a0, unsigned a1, unsigned a2, unsigned a3,
    unsigned b0, unsigned b1)
{
    asm volatile(
        "mma.sync.aligned.m16n8k8.row.col.f32.tf32.tf32.f32 "
        "{%0,%1,%2,%3}, {%4,%5,%6,%7}, {%8,%9}, {%0,%1,%2,%3};"
        : "+f"(c0), "+f"(c1), "+f"(c2), "+f"(c3)
        : "r"(a0), "r"(a1), "r"(a2), "r"(a3), "r"(b0), "r"(b1));
}

// ---------------- cp.async helpers ------------------------------------------
__device__ __forceinline__ void cpa16(void* dst, const void* src) {
    unsigned d = (unsigned)__cvta_generic_to_shared(dst);
    asm volatile("cp.async.cg.shared.global [%0], [%1], 16;" :: "r"(d), "l"(src));
}
#define CP_COMMIT()  asm volatile("cp.async.commit_group;")
#define CP_WAIT(N)   asm volatile("cp.async.wait_group %0;" :: "n"(N))

// ---------------- scratch (device globals; no allocation allowed) ----------
__device__ float g_xn  [ROWS * DD];
__device__ float g_qkv [ROWS * 3 * DD];
__device__ float g_q   [BB * HH * SS * HD];  // [b,h,s,d]
__device__ float g_k   [BB * HH * SS * HD];
__device__ float g_v   [BB * HH * SS * HD];
__device__ float g_attn[ROWS * DD];          // [b,s,h*64+d]
__device__ int   g_ticket;

// ---------------- kernel 1: row LayerNorm over D=1024 ---------------------
__global__ __launch_bounds__(256) void ln_kernel(
    const float* __restrict__ x, const float* __restrict__ scale,
    const float* __restrict__ bias, float* __restrict__ y)
{
    __shared__ float sh[8];
    const int t = threadIdx.x;
    const size_t row = blockIdx.x;
    const float* xr = x + row * DD;

    float v0 = xr[t], v1 = xr[t + 256], v2 = xr[t + 512], v3 = xr[t + 768];

    float s = v0 + v1 + v2 + v3;
    #pragma unroll
    for (int o = 16; o; o >>= 1) s += __shfl_xor_sync(0xffffffffu, s, o);
    if ((t & 31) == 0) sh[t >> 5] = s;
    __syncthreads();
    float tot = 0.f;
    #pragma unroll
    for (int i = 0; i < 8; i++) tot += sh[i];
    const float mean = tot * (1.f / 1024.f);

    float a0 = v0 - mean, a1 = v1 - mean, a2 = v2 - mean, a3 = v3 - mean;
    float sq = a0*a0 + a1*a1 + a2*a2 + a3*a3;
    #pragma unroll
    for (int o = 16; o; o >>= 1) sq += __shfl_xor_sync(0xffffffffu, sq, o);
    __syncthreads();
    if ((t & 31) == 0) sh[t >> 5] = sq;
    __syncthreads();
    float tsq = 0.f;
    #pragma unroll
    for (int i = 0; i < 8; i++) tsq += sh[i];
    const float rstd = rsqrtf(tsq * (1.f / 1024.f) + EPS);

    float* yr = y + row * DD;
    yr[t      ] = a0 * rstd * scale[t      ] + bias[t      ];
    yr[t + 256] = a1 * rstd * scale[t + 256] + bias[t + 256];
    yr[t + 512] = a2 * rstd * scale[t + 512] + bias[t + 512];
    yr[t + 768] = a3 * rstd * scale[t + 768] + bias[t + 768];
}

// ---------------- kernel 2: 3xTF32 tensor-core GEMM + bias ----------------
// EXACT R11 layout (136-float padded rows, measured conflict-free fills and
// fragment loads) with ONE change: register prefetch of the next k-tile's
// LDGs issued before compute, STS after compute. Hides global-load latency
// that R11 exposed every iteration. Smem layout/compute byte-identical.
#define GKT 16
__global__ __launch_bounds__(256) void sgemm_tf32(
    const float* __restrict__ A, const float* __restrict__ B,
    const float* __restrict__ bias, float* __restrict__ C,
    int M, int N, int K)
{
    __shared__ float AsH[GKT][136], AsL[GKT][136];
    __shared__ float BsH[GKT][136], BsL[GKT][136];

    const int tid = threadIdx.x;
    const int wid = tid >> 5;
    const int lane = tid & 31;
    const int g = lane >> 2;          // 0..7
    const int t = lane & 3;           // 0..3
    const int warp_m = wid >> 2;      // 0..1
    const int warp_n = wid & 3;       // 0..3
    const int rowBase = blockIdx.y * 128;
    const int colBase = blockIdx.x * 128;

    // fill assignments (same as R11)
    const int am = tid >> 1;              // 0..127 (A row within tile)
    const int ak = (tid & 1) * 8;         // 0 or 8 (A k-offset)
    const int bk = tid >> 4;              // 0..15  (B k-row)
    const int bn = (tid & 15) * 8;        // 0..120 (B n-offset)

    const float* Ag = A + (size_t)(rowBase + am) * K + ak;
    const float* Bg = B + (size_t)bk * N + colBase + bn;

    float c[4][4][4];
    #pragma unroll
    for (int mi = 0; mi < 4; mi++)
        #pragma unroll
        for (int ni = 0; ni < 4; ni++)
            #pragma unroll
            for (int e = 0; e < 4; e++) c[mi][ni][e] = 0.f;

    const int NIT = K >> 4;

    float4 ra0 = *(const float4*)(Ag);
    float4 ra1 = *(const float4*)(Ag + 4);
    float4 rb0 = *(const float4*)(Bg);
    float4 rb1 = *(const float4*)(Bg + 4);

    // fill tile 0 (identical transform to R11)
    {
        float va[8] = {ra0.x, ra0.y, ra0.z, ra0.w, ra1.x, ra1.y, ra1.z, ra1.w};
        #pragma unroll
        for (int e = 0; e < 8; e++) {
            float h = cvt_tf32(va[e]);
            AsH[ak + e][am] = h; AsL[ak + e][am] = va[e] - h;
        }
        float4 hh, ll;
        hh.x = cvt_tf32(rb0.x); ll.x = rb0.x - hh.x;
        hh.y = cvt_tf32(rb0.y); ll.y = rb0.y - hh.y;
        hh.z = cvt_tf32(rb0.z); ll.z = rb0.z - hh.z;
        hh.w = cvt_tf32(rb0.w); ll.w = rb0.w - hh.w;
        *(float4*)&BsH[bk][bn] = hh;  *(float4*)&BsL[bk][bn] = ll;
        hh.x = cvt_tf32(rb1.x); ll.x = rb1.x - hh.x;
        hh.y = cvt_tf32(rb1.y); ll.y = rb1.y - hh.y;
        hh.z = cvt_tf32(rb1.z); ll.z = rb1.z - hh.z;
        hh.w = cvt_tf32(rb1.w); ll.w = rb1.w - hh.w;
        *(float4*)&BsH[bk][bn + 4] = hh;  *(float4*)&BsL[bk][bn + 4] = ll;
    }
    __syncthreads();

    for (int i = 0; i < NIT; i++) {
        // prefetch next tile's globals BEFORE compute (latency hidden)
        if (i + 1 < NIT) {
            const int k0 = (i + 1) * GKT;
            ra0 = *(const float4*)(Ag + k0);
            ra1 = *(const float4*)(Ag + k0 + 4);
            rb0 = *(const float4*)(Bg + (size_t)k0 * N);
            rb1 = *(const float4*)(Bg + (size_t)k0 * N + 4);
        }

        // ---- compute (identical to R11) ----
        #pragma unroll
        for (int ks = 0; ks < GKT; ks += 8) {
            unsigned aH[4][4], aL[4][4], bH[4][2], bL[4][2];
            #pragma unroll
            for (int mi = 0; mi < 4; mi++) {
                const int r = warp_m * 64 + mi * 16 + g;
                aH[mi][0] = __float_as_uint(AsH[ks + t    ][r    ]);
                aH[mi][1] = __float_as_uint(AsH[ks + t    ][r + 8]);
                aH[mi][2] = __float_as_uint(AsH[ks + t + 4][r    ]);
                aH[mi][3] = __float_as_uint(AsH[ks + t + 4][r + 8]);
                aL[mi][0] = __float_as_uint(AsL[ks + t    ][r    ]);
                aL[mi][1] = __float_as_uint(AsL[ks + t    ][r + 8]);
                aL[mi][2] = __float_as_uint(AsL[ks + t + 4][r    ]);
                aL[mi][3] = __float_as_uint(AsL[ks + t + 4][r + 8]);
            }
            #pragma unroll
            for (int ni = 0; ni < 4; ni++) {
                const int n = warp_n * 32 + ni * 8 + g;
                bH[ni][0] = __float_as_uint(BsH[ks + t    ][n]);
                bH[ni][1] = __float_as_uint(BsH[ks + t + 4][n]);
                bL[ni][0] = __float_as_uint(BsL[ks + t    ][n]);
                bL[ni][1] = __float_as_uint(BsL[ks + t + 4][n]);
            }
            #pragma unroll
            for (int mi = 0; mi < 4; mi++)
                #pragma unroll
                for (int ni = 0; ni < 4; ni++)
                    mma_tf32(c[mi][ni][0], c[mi][ni][1], c[mi][ni][2], c[mi][ni][3],
                             aH[mi][0], aH[mi][1], aH[mi][2], aH[mi][3],
                             bH[ni][0], bH[ni][1]);
            #pragma unroll
            for (int mi = 0; mi < 4; mi++)
                #pragma unroll
                for (int ni = 0; ni < 4; ni++)
                    mma_tf32(c[mi][ni][0], c[mi][ni][1], c[mi][ni][2], c[mi][ni][3],
                             aH[mi][0], aH[mi][1], aH[mi][2], aH[mi][3],
                             bL[ni][0], bL[ni][1]);
            #pragma unroll
            for (int mi = 0; mi < 4; mi++)
                #pragma unroll
                for (int ni = 0; ni < 4; ni++)
                    mma_tf32(c[mi][ni][0], c[mi][ni][1], c[mi][ni][2], c[mi][ni][3],
                             aL[mi][0], aL[mi][1], aL[mi][2], aL[mi][3],
                             bH[ni][0], bH[ni][1]);
        }

        if (i + 1 < NIT) {
            __syncthreads();   // everyone done reading current tile
            // ---- store prefetched tile (identical transform to R11) ----
            float va[8] = {ra0.x, ra0.y, ra0.z, ra0.w, ra1.x, ra1.y, ra1.z, ra1.w};
            #pragma unroll
            for (int e = 0; e < 8; e++) {
                float h = cvt_tf32(va[e]);
                AsH[ak + e][am] = h; AsL[ak + e][am] = va[e] - h;
            }
            float4 hh, ll;
            hh.x = cvt_tf32(rb0.x); ll.x = rb0.x - hh.x;
            hh.y = cvt_tf32(rb0.y); ll.y = rb0.y - hh.y;
            hh.z = cvt_tf32(rb0.z); ll.z = rb0.z - hh.z;
            hh.w = cvt_tf32(rb0.w); ll.w = rb0.w - hh.w;
            *(float4*)&BsH[bk][bn] = hh;  *(float4*)&BsL[bk][bn] = ll;
            hh.x = cvt_tf32(rb1.x); ll.x = rb1.x - hh.x;
            hh.y = cvt_tf32(rb1.y); ll.y = rb1.y - hh.y;
            hh.z = cvt_tf32(rb1.z); ll.z = rb1.z - hh.z;
            hh.w = cvt_tf32(rb1.w); ll.w = rb1.w - hh.w;
            *(float4*)&BsH[bk][bn + 4] = hh;  *(float4*)&BsL[bk][bn + 4] = ll;
            __syncthreads();   // new tile visible
        }
    }

    // ---- epilogue: bias + store (identical to R11) ----
    #pragma unroll
    for (int ni = 0; ni < 4; ni++) {
        const int col = colBase + warp_n * 32 + ni * 8 + 2 * t;
        const float2 bb = *(const float2*)(bias + col);
        #pragma unroll
        for (int mi = 0; mi < 4; mi++) {
            const int row = rowBase + warp_m * 64 + mi * 16 + g;
            float2 o0, o1;
            o0.x = c[mi][ni][0] + bb.x;  o0.y = c[mi][ni][1] + bb.y;
            o1.x = c[mi][ni][2] + bb.x;  o1.y = c[mi][ni][3] + bb.y;
            *(float2*)(C + (size_t)row * N + col)       = o0;
            *(float2*)(C + (size_t)(row + 8) * N + col) = o1;
        }
    }
}

// ---------------- kernel 3: per-head LN (q,k) + RoPE + transpose ----------
__global__ __launch_bounds__(128) void qk_rope_kernel(
    const float* __restrict__ qkv,
    const float* __restrict__ q_scale, const float* __restrict__ k_scale,
    float* __restrict__ Q, float* __restrict__ K, float* __restrict__ V)
{
    const int w = blockIdx.x * 4 + (threadIdx.x >> 5);
    const int lane = threadIdx.x & 31;
    const int h = w % HH;
    const int s = (w / HH) % SS;
    const int b = w / (HH * SS);

    const float* row = qkv + (size_t)(b * SS + s) * (3 * DD) + h * HD;
    float q0 = row[lane],        q1 = row[lane + 32];
    float k0 = row[DD + lane],   k1 = row[DD + lane + 32];
    float v0 = row[2*DD + lane], v1 = row[2*DD + lane + 32];

    float mu = q0 + q1;
    #pragma unroll
    for (int o = 16; o; o >>= 1) mu += __shfl_xor_sync(0xffffffffu, mu, o);
    mu *= (1.f / 64.f);
    float a0 = q0 - mu, a1 = q1 - mu;
    float var = a0 * a0 + a1 * a1;
    #pragma unroll
    for (int o = 16; o; o >>= 1) var += __shfl_xor_sync(0xffffffffu, var, o);
    float r = rsqrtf(var * (1.f / 64.f) + EPS);
    float yq0 = a0 * r * q_scale[lane], yq1 = a1 * r * q_scale[lane + 32];

    mu = k0 + k1;
    #pragma unroll
    for (int o = 16; o; o >>= 1) mu += __shfl_xor_sync(0xffffffffu, mu, o);
    mu *= (1.f / 64.f);
    a0 = k0 - mu; a1 = k1 - mu;
    var = a0 * a0 + a1 * a1;
    #pragma unroll
    for (int o = 16; o; o >>= 1) var += __shfl_xor_sync(0xffffffffu, var, o);
    r = rsqrtf(var * (1.f / 64.f) + EPS);
    float yk0 = a0 * r * k_scale[lane], yk1 = a1 * r * k_scale[lane + 32];

    const float invf = (float)exp(-(double)(2 * lane) / 64.0 * log(10000.0));
    const float ang = (float)s * invf;
    const float c = cosf(ang), sn = sinf(ang);

    float oq0 = yq0 * c - yq1 * sn;
    float oq1 = yq1 * c + yq0 * sn;
    float ok0 = yk0 * c - yk1 * sn;
    float ok1 = yk1 * c + yk0 * sn;

    const size_t base = ((size_t)(b * HH + h) * SS + s) * HD;
    Q[base + lane] = oq0; Q[base + lane + 32] = oq1;
    K[base + lane] = ok0; K[base + lane + 32] = ok1;
    V[base + lane] = v0;  V[base + lane + 32] = v1;
}

// ---------------- kernel 4: flash attention v5 (measured 839us, R12) -------
#define FL_STAGE 2304        // ull2 per stage (K 1152 + V 1152)
#define FL_VOFF  1152

__device__ __forceinline__ void fl_copy(ulonglong2* dst,
    const ulonglong2* Kg, const ulonglong2* Vg, int tid)
{
    #pragma unroll
    for (int i = 0; i < 8; i++) {
        const int e  = tid + i * 128;
        const int j  = e >> 4;
        const int qq = e & 15;
        const int di = j * 18 + (qq >> 3) * 9 + (qq & 7);
        cpa16(dst + di, Kg + e);
        cpa16(dst + FL_VOFF + di, Vg + e);
    }
    CP_COMMIT();
}

__global__ __launch_bounds__(128, 2) void flash_kernel(
    const float* __restrict__ Q, const float* __restrict__ K,
    const float* __restrict__ V, float* __restrict__ O)
{
    extern __shared__ ulonglong2 dsm[];
    __shared__ int s_tile;

    const int tid = threadIdx.x;
    const int m = tid >> 1;
    const int h = tid & 1;
    const float QSCALE = 0.125f * 1.44269504088896340736f;
    const u64 qsc = pack2(QSCALE, QSCALE);

    for (;;) {
        if (tid == 0) s_tile = atomicAdd(&g_ticket, 1);
        __syncthreads();
        const int tile = s_tile;
        if (tile >= 512) break;

        const int bh = tile >> 4;
        const int q0 = (tile & 15) * 128;
        const int rA = q0 + m;
        const int rB = q0 + 64 + m;

        const ulonglong2* Kg0 = (const ulonglong2*)(K + (size_t)bh * SS * HD);
        const ulonglong2* Vg0 = (const ulonglong2*)(V + (size_t)bh * SS * HD);

        fl_copy(dsm, Kg0, Vg0, tid);

        u64 qA[16], qB[16];
        {
            const ulonglong2* Qa = (const ulonglong2*)(Q + ((size_t)bh * SS + rA) * HD + h * 32);
            const ulonglong2* Qb = (const ulonglong2*)(Q + ((size_t)bh * SS + rB) * HD + h * 32);
            #pragma unroll
            for (int i = 0; i < 8; i++) {
                ulonglong2 ta = Qa[i];
                qA[2*i] = mul2(ta.x, qsc); qA[2*i+1] = mul2(ta.y, qsc);
                ulonglong2 tb = Qb[i];
                qB[2*i] = mul2(tb.x, qsc); qB[2*i+1] = mul2(tb.y, qsc);
            }
        }

        u64 accA[16], accB[16];
        #pragma unroll
        for (int i = 0; i < 16; i++) { accA[i] = 0ull; accB[i] = 0ull; }
        float la = 0.f, lb = 0.f;

        for (int kt = 0; kt < SS / 64; kt++) {
            if (kt + 1 < SS / 64) {
                fl_copy(dsm + ((kt + 1) & 1) * FL_STAGE,
                        Kg0 + (kt + 1) * 1024, Vg0 + (kt + 1) * 1024, tid);
                CP_WAIT(1);
            } else {
                CP_WAIT(0);
            }
            __syncthreads();

            const ulonglong2* buf = dsm + (kt & 1) * FL_STAGE;
            const ulonglong2* Ksh = buf + h * 9;
            const ulonglong2* Vsh = buf + FL_VOFF + h * 9;

            #pragma unroll 1
            for (int jt = 0; jt < 64; jt += 8) {
                u64 cA[8], cB[8];
                #pragma unroll
                for (int j = 0; j < 8; j++) {
                    const ulonglong2* kr = Ksh + (jt + j) * 18;
                    u64 a = 0ull, b = 0ull;
                    #pragma unroll
                    for (int k4 = 0; k4 < 8; k4++) {
                        ulonglong2 kk = kr[k4];
                        a = fma2(qA[2*k4  ], kk.x, a);
                        a = fma2(qA[2*k4+1], kk.y, a);
                        b = fma2(qB[2*k4  ], kk.x, b);
                        b = fma2(qB[2*k4+1], kk.y, b);
                    }
                    cA[j] = a; cB[j] = b;
                }

                float pA[8], pB[8];
                #pragma unroll
                for (int j = 0; j < 8; j++) {
                    float sa = lo2(cA[j]) + hi2(cA[j]);
                    float sb = lo2(cB[j]) + hi2(cB[j]);
                    sa += __shfl_xor_sync(0xffffffffu, sa, 1);
                    sb += __shfl_xor_sync(0xffffffffu, sb, 1);
                    pA[j] = ex2(sa);
                    pB[j] = ex2(sb);
                }
                #pragma unroll
                for (int j = 0; j < 8; j++) { la += pA[j]; lb += pB[j]; }

                #pragma unroll
                for (int j = 0; j < 8; j++) {
                    const ulonglong2* vr = Vsh + (jt + j) * 18;
                    const u64 ppa = pack2(pA[j], pA[j]);
                    const u64 ppb = pack2(pB[j], pB[j]);
                    #pragma unroll
                    for (int d4 = 0; d4 < 8; d4++) {
                        ulonglong2 vv = vr[d4];
                        accA[2*d4  ] = fma2(ppa, vv.x, accA[2*d4  ]);
                        accA[2*d4+1] = fma2(ppa, vv.y, accA[2*d4+1]);
                        accB[2*d4  ] = fma2(ppb, vv.x, accB[2*d4  ]);
                        accB[2*d4+1] = fma2(ppb, vv.y, accB[2*d4+1]);
                    }
                }
            }
            __syncthreads();
        }

        const int b = bh >> 4, hh = bh & 15;
        const u64 pia = pack2(1.f / la, 1.f / la);
        const u64 pib = pack2(1.f / lb, 1.f / lb);
        ulonglong2* Oa = (ulonglong2*)(O + ((size_t)(b * SS + rA)) * DD + hh * HD + h * 32);
        ulonglong2* Ob = (ulonglong2*)(O + ((size_t)(b * SS + rB)) * DD + hh * HD + h * 32);
        #pragma unroll
        for (int i = 0; i < 8; i++) {
            ulonglong2 ta, tb;
            ta.x = mul2(accA[2*i], pia); ta.y = mul2(accA[2*i+1], pia);
            tb.x = mul2(accB[2*i], pib); tb.y = mul2(accB[2*i+1], pib);
            Oa[i] = ta;
            Ob[i] = tb;
        }
    }
}

// ---------------- launcher -------------------------------------------------
extern "C" void kernel_launch(void* const* d_in, const int* in_sizes, int n_in,
                              void* d_out, int out_size)
{
    const float* x        = (const float*)d_in[0];
    const float* w_qkv    = (const float*)d_in[1];
    const float* b_qkv    = (const float*)d_in[2];
    const float* w_out    = (const float*)d_in[3];
    const float* b_out    = (const float*)d_in[4];
    const float* ln_scale = (const float*)d_in[5];
    const float* ln_bias  = (const float*)d_in[6];
    const float* q_scale  = (const float*)d_in[7];
    const float* k_scale  = (const float*)d_in[8];
    float* out = (float*)d_out;

    float *xn, *qkv, *q, *k, *v, *attn;
    int* ticket;
    cudaGetSymbolAddress((void**)&xn,     g_xn);
    cudaGetSymbolAddress((void**)&qkv,    g_qkv);
    cudaGetSymbolAddress((void**)&q,      g_q);
    cudaGetSymbolAddress((void**)&k,      g_k);
    cudaGetSymbolAddress((void**)&v,      g_v);
    cudaGetSymbolAddress((void**)&attn,   g_attn);
    cudaGetSymbolAddress((void**)&ticket, g_ticket);

    cudaFuncSetAttribute(flash_kernel,
        cudaFuncAttributeMaxDynamicSharedMemorySize, 2 * FL_STAGE * 16);

    // 1) input layernorm
    ln_kernel<<<ROWS, 256>>>(x, ln_scale, ln_bias, xn);

    // 2) QKV projection: [4096,1024] @ [1024,3072]  (3xTF32 + reg prefetch)
    sgemm_tf32<<<dim3(3 * DD / 128, ROWS / 128), 256>>>(xn, w_qkv, b_qkv, qkv,
                                                        ROWS, 3 * DD, DD);

    // 3) head LN + RoPE + layout change
    qk_rope_kernel<<<(BB * SS * HH) / 4, 128>>>(qkv, q_scale, k_scale, q, k, v);

    // 4) attention: persistent grid + atomic tile scheduler + cp.async
    cudaMemsetAsync(ticket, 0, sizeof(int));
    flash_kernel<<<304, 128, 2 * FL_STAGE * 16>>>(q, k, v, attn);

    // 5) output projection: [4096,1024] @ [1024,1024]  (3xTF32 + reg prefetch)
    sgemm_tf32<<<dim3(DD / 128, ROWS / 128), 256>>>(attn, w_out, b_out, out,
                                                    ROWS, DD, DD);
}